// round 2
// baseline (speedup 1.0000x reference)
#include <cuda_runtime.h>
#include <mma.h>

using namespace nvcuda;

#define TSTEPS 512
#define BATCH  128
#define INP    1024
#define HID    1024
#define NG     4096   // 4*HID
#define NLAYER 2
#define NCTA   64     // persistent kernel CTAs (all co-resident on 148 SMs)

// ---------------- device scratch (no dynamic allocation allowed) ----------------
__device__ float g_gates[(size_t)TSTEPS * BATCH * NG];   // 1 GiB input projections
__device__ float g_hseq [(size_t)TSTEPS * BATCH * HID];  // layer-0 output sequence
__device__ float g_hbuf [2][BATCH * HID];                // ping-pong hidden state
__device__ unsigned int g_count;                         // global barrier counter

__device__ __forceinline__ float to_tf32(float x) {
    unsigned int u;
    asm("cvt.rna.tf32.f32 %0, %1;" : "=r"(u) : "f"(x));
    return __uint_as_float(u);
}
__device__ __forceinline__ float sigmoidf_(float x) {
    return 1.f / (1.f + __expf(-x));
}

// =================================================================================
// Input GEMM: C[M,N] = A[M,K] @ W[K,N]   (tf32 tensor cores, fp32 accum)
// BM=128 BN=128 BK=16, 256 threads, warp tile 64x32
// =================================================================================
__global__ void gemm_input_tf32(const float* __restrict__ A, const float* __restrict__ W,
                                float* __restrict__ C, int K, int N)
{
    __shared__ float As[128][20];
    __shared__ float Bs[16][132];

    const int tid  = threadIdx.x;
    const int warp = tid >> 5;
    const int warp_m = warp >> 2;
    const int warp_n = warp & 3;
    const int bm = blockIdx.y, bn = blockIdx.x;

    const int arow = tid >> 1,  acol = (tid & 1) * 8;
    const int brow = tid >> 4,  bcol = (tid & 15) * 8;

    const float* Ag = A + (size_t)(bm * 128 + arow) * K + acol;
    const float* Wg = W + (size_t)brow * N + bn * 128 + bcol;

    wmma::fragment<wmma::accumulator, 16, 16, 8, float> acc[4][2];
#pragma unroll
    for (int i = 0; i < 4; i++)
#pragma unroll
        for (int j = 0; j < 2; j++) wmma::fill_fragment(acc[i][j], 0.f);

    for (int kt = 0; kt < K; kt += 16) {
        float4 a0 = *(const float4*)(Ag + kt);
        float4 a1 = *(const float4*)(Ag + kt + 4);
        float4 b0 = *(const float4*)(Wg + (size_t)kt * N);
        float4 b1 = *(const float4*)(Wg + (size_t)kt * N + 4);
        __syncthreads();
        As[arow][acol + 0] = to_tf32(a0.x); As[arow][acol + 1] = to_tf32(a0.y);
        As[arow][acol + 2] = to_tf32(a0.z); As[arow][acol + 3] = to_tf32(a0.w);
        As[arow][acol + 4] = to_tf32(a1.x); As[arow][acol + 5] = to_tf32(a1.y);
        As[arow][acol + 6] = to_tf32(a1.z); As[arow][acol + 7] = to_tf32(a1.w);
        Bs[brow][bcol + 0] = to_tf32(b0.x); Bs[brow][bcol + 1] = to_tf32(b0.y);
        Bs[brow][bcol + 2] = to_tf32(b0.z); Bs[brow][bcol + 3] = to_tf32(b0.w);
        Bs[brow][bcol + 4] = to_tf32(b1.x); Bs[brow][bcol + 5] = to_tf32(b1.y);
        Bs[brow][bcol + 6] = to_tf32(b1.z); Bs[brow][bcol + 7] = to_tf32(b1.w);
        __syncthreads();
#pragma unroll
        for (int ks = 0; ks < 16; ks += 8) {
            wmma::fragment<wmma::matrix_a, 16, 16, 8, wmma::precision::tf32, wmma::row_major> fa[4];
            wmma::fragment<wmma::matrix_b, 16, 16, 8, wmma::precision::tf32, wmma::row_major> fb[2];
#pragma unroll
            for (int i = 0; i < 4; i++)
                wmma::load_matrix_sync(fa[i], &As[warp_m * 64 + i * 16][ks], 20);
#pragma unroll
            for (int j = 0; j < 2; j++)
                wmma::load_matrix_sync(fb[j], &Bs[ks][warp_n * 32 + j * 16], 132);
#pragma unroll
            for (int i = 0; i < 4; i++)
#pragma unroll
                for (int j = 0; j < 2; j++)
                    wmma::mma_sync(acc[i][j], fa[i], fb[j], acc[i][j]);
        }
    }

    const size_t row0 = (size_t)bm * 128 + warp_m * 64;
    const size_t col0 = (size_t)bn * 128 + warp_n * 32;
#pragma unroll
    for (int i = 0; i < 4; i++)
#pragma unroll
        for (int j = 0; j < 2; j++)
            wmma::store_matrix_sync(C + (row0 + i * 16) * N + col0 + j * 16,
                                    acc[i][j], N, wmma::mem_row_major);
}

// =================================================================================
// Init: zero h buffer 0 and the global barrier counter
// =================================================================================
__global__ void lstm_init()
{
    const int i = blockIdx.x * blockDim.x + threadIdx.x;
    if (i == 0) g_count = 0;
    g_hbuf[0][i] = 0.f;
}

// =================================================================================
// Persistent recurrence kernel: one launch runs all 512 timesteps of a layer.
// 64 CTAs x 256 threads. CTA (bm, bj): rows bm*64..+64, j-cols bj*32..+32.
// Each CTA computes its 64x128 gate tile (4 gates x 32 cols) via tf32 wmma,
// accumulating on top of the precomputed x@W_ih slice, then applies the cell
// (c kept in registers), writes h to ping-pong global + sequence output,
// then crosses a global generation barrier.
// =================================================================================
__global__ void __launch_bounds__(256, 1) lstm_recur(
    const float* __restrict__ Whh,     // [HID, NG]
    const float* __restrict__ gates,   // [T, B, NG] precomputed x@W_ih
    const float* __restrict__ b1, const float* __restrict__ b2,
    float* __restrict__ seq,           // [T, B, HID]
    float* __restrict__ hT, float* __restrict__ cT)
{
    // union smem: As/Bs (GEMM staging) overlapped with Gs (gate tile for cell)
    // As: 64x36 floats @0 (9216B), Bs: 32x132 @9216 (16896B)  -> 26112B
    // Gs: 64x132 floats (33792B)
    __shared__ __align__(16) char smem_raw[64 * 132 * 4];
    float (*As)[36]  = reinterpret_cast<float (*)[36]>(smem_raw);
    float (*Bs)[132] = reinterpret_cast<float (*)[132]>(smem_raw + 64 * 36 * 4);
    float (*Gs)[132] = reinterpret_cast<float (*)[132]>(smem_raw);

    const int tid  = threadIdx.x;
    const int warp = tid >> 5;
    const int warp_m = warp >> 2;      // 0..1
    const int gate   = warp & 3;       // 0..3 : each warp owns one gate's 32-wide strip
    const int bx = blockIdx.x;
    const int bm = bx >> 5;            // 0..1
    const int bj = bx & 31;            // 0..31
    const int row0 = bm * 64;
    const int j0   = bj * 32;

    // A staging: 512 float4 (64 rows x 8), 2 per thread
    const int a_idx0 = tid * 2;
    // B staging: 1024 float4 (32 rows x 32), 4 per thread
    const int b_idx0 = tid * 4;

    // cell mapping: thread -> col cj, 8 rows starting cr0
    const int cj  = tid & 31;
    const int cr0 = (tid >> 5) * 8;

    float creg[8];
#pragma unroll
    for (int i = 0; i < 8; i++) creg[i] = 0.f;

    float bias[4];
#pragma unroll
    for (int g = 0; g < 4; g++)
        bias[g] = b1[g * HID + j0 + cj] + b2[g * HID + j0 + cj];

    for (int t = 0; t < TSTEPS; ++t) {
        const float* hin  = g_hbuf[t & 1];
        float*       hout = g_hbuf[(t + 1) & 1];
        const float* Gt   = gates + (size_t)t * BATCH * NG;

        // accumulators initialized from precomputed input projection
        wmma::fragment<wmma::accumulator, 16, 16, 8, float> acc[2][2];
#pragma unroll
        for (int i = 0; i < 2; i++)
#pragma unroll
            for (int j = 0; j < 2; j++)
                wmma::load_matrix_sync(acc[i][j],
                    Gt + (size_t)(row0 + warp_m * 32 + i * 16) * NG
                       + (size_t)gate * HID + j0 + j * 16,
                    NG, wmma::mem_row_major);

        // prefetch chunk 0 into registers
        float4 rA[2], rB[4];
#pragma unroll
        for (int u = 0; u < 2; u++) {
            int idx = a_idx0 + u, r = idx >> 3, c4 = idx & 7;
            rA[u] = *(const float4*)(hin + (size_t)(row0 + r) * HID + c4 * 4);
        }
#pragma unroll
        for (int u = 0; u < 4; u++) {
            int idx = b_idx0 + u, r = idx >> 5, c4 = idx & 31;
            int g = c4 >> 3, j4 = c4 & 7;
            rB[u] = *(const float4*)(Whh + (size_t)r * NG + (size_t)g * HID + j0 + j4 * 4);
        }

        for (int kt = 0; kt < HID; kt += 32) {
            __syncthreads();   // smem consumers of previous phase done
#pragma unroll
            for (int u = 0; u < 2; u++) {
                int idx = a_idx0 + u, r = idx >> 3, c4 = idx & 7;
                As[r][c4 * 4 + 0] = to_tf32(rA[u].x);
                As[r][c4 * 4 + 1] = to_tf32(rA[u].y);
                As[r][c4 * 4 + 2] = to_tf32(rA[u].z);
                As[r][c4 * 4 + 3] = to_tf32(rA[u].w);
            }
#pragma unroll
            for (int u = 0; u < 4; u++) {
                int idx = b_idx0 + u, r = idx >> 5, c4 = idx & 31;
                int g = c4 >> 3, j4 = c4 & 7;
                Bs[r][g * 32 + j4 * 4 + 0] = to_tf32(rB[u].x);
                Bs[r][g * 32 + j4 * 4 + 1] = to_tf32(rB[u].y);
                Bs[r][g * 32 + j4 * 4 + 2] = to_tf32(rB[u].z);
                Bs[r][g * 32 + j4 * 4 + 3] = to_tf32(rB[u].w);
            }
            __syncthreads();

            // prefetch next chunk while computing this one
            const int kn = kt + 32;
            if (kn < HID) {
#pragma unroll
                for (int u = 0; u < 2; u++) {
                    int idx = a_idx0 + u, r = idx >> 3, c4 = idx & 7;
                    rA[u] = *(const float4*)(hin + (size_t)(row0 + r) * HID + kn + c4 * 4);
                }
#pragma unroll
                for (int u = 0; u < 4; u++) {
                    int idx = b_idx0 + u, r = idx >> 5, c4 = idx & 31;
                    int g = c4 >> 3, j4 = c4 & 7;
                    rB[u] = *(const float4*)(Whh + (size_t)(kn + r) * NG + (size_t)g * HID + j0 + j4 * 4);
                }
            }

#pragma unroll
            for (int ks = 0; ks < 32; ks += 8) {
                wmma::fragment<wmma::matrix_a, 16, 16, 8, wmma::precision::tf32, wmma::row_major> fa[2];
                wmma::fragment<wmma::matrix_b, 16, 16, 8, wmma::precision::tf32, wmma::row_major> fb[2];
#pragma unroll
                for (int i = 0; i < 2; i++)
                    wmma::load_matrix_sync(fa[i], &As[warp_m * 32 + i * 16][ks], 36);
#pragma unroll
                for (int j = 0; j < 2; j++)
                    wmma::load_matrix_sync(fb[j], &Bs[ks][gate * 32 + j * 16], 132);
#pragma unroll
                for (int i = 0; i < 2; i++)
#pragma unroll
                    for (int j = 0; j < 2; j++)
                        wmma::mma_sync(acc[i][j], fa[i], fb[j], acc[i][j]);
            }
        }

        __syncthreads();   // done reading As/Bs; Gs aliases them
#pragma unroll
        for (int i = 0; i < 2; i++)
#pragma unroll
            for (int j = 0; j < 2; j++)
                wmma::store_matrix_sync(&Gs[warp_m * 32 + i * 16][gate * 32 + j * 16],
                                        acc[i][j], 132, wmma::mem_row_major);
        __syncthreads();

        // ---- LSTM cell (c in registers) ----
#pragma unroll
        for (int i = 0; i < 8; i++) {
            const int r = cr0 + i;
            float zi = Gs[r][0 * 32 + cj] + bias[0];
            float zf = Gs[r][1 * 32 + cj] + bias[1];
            float zg = Gs[r][2 * 32 + cj] + bias[2];
            float zo = Gs[r][3 * 32 + cj] + bias[3];

            float ig = sigmoidf_(zi);
            float fg = sigmoidf_(zf);
            float gg = tanhf(zg);
            float og = sigmoidf_(zo);

            float cn = fg * creg[i] + ig * gg;
            float hn = og * tanhf(cn);
            creg[i] = cn;

            const size_t gidx = (size_t)(row0 + r) * HID + j0 + cj;
            hout[gidx] = hn;
            seq[(size_t)t * BATCH * HID + gidx] = hn;
            if (t == TSTEPS - 1) { hT[gidx] = hn; cT[gidx] = cn; }
        }

        // ---- global generation barrier ----
        __threadfence();
        __syncthreads();
        if (tid == 0) {
            atomicAdd(&g_count, 1u);
            const unsigned target = (unsigned)(t + 1) * gridDim.x;
            while (atomicAdd(&g_count, 0u) < target) { }
            __threadfence();
        }
        __syncthreads();
    }
}

// =================================================================================
extern "C" void kernel_launch(void* const* d_in, const int* in_sizes, int n_in,
                              void* d_out, int out_size)
{
    const float* x   = (const float*)d_in[0];  // [T, B, IN]
    const float* wih = (const float*)d_in[1];  // [L, IN, 4H]
    const float* whh = (const float*)d_in[2];  // [L, H, 4H]
    const float* bih = (const float*)d_in[3];  // [L, 4H]
    const float* bhh = (const float*)d_in[4];  // [L, 4H]
    float* out = (float*)d_out;

    float *gates, *hseq;
    cudaGetSymbolAddress((void**)&gates, g_gates);
    cudaGetSymbolAddress((void**)&hseq,  g_hseq);

    // output layout: [T,B,H] last-layer h_seq | [L,B,H] h_T | [L,B,H] c_T
    float* hT_base = out + (size_t)TSTEPS * BATCH * HID;
    float* cT_base = hT_base + (size_t)NLAYER * BATCH * HID;

    const int MT = TSTEPS * BATCH;  // 65536

    for (int l = 0; l < NLAYER; ++l) {
        const float* A   = l ? hseq : x;
        const float* Wih = wih + (size_t)l * INP * NG;
        const float* Whh = whh + (size_t)l * HID * NG;
        const float* B1  = bih + (size_t)l * NG;
        const float* B2  = bhh + (size_t)l * NG;
        float* seq = l ? out : hseq;
        float* hT  = hT_base + (size_t)l * BATCH * HID;
        float* cT  = cT_base + (size_t)l * BATCH * HID;

        // 1) parallel input projection over all timesteps
        gemm_input_tf32<<<dim3(NG / 128, MT / 128), 256>>>(A, Wih, gates, INP, NG);

        // 2) reset h0 and barrier counter
        lstm_init<<<(BATCH * HID) / 256, 256>>>();

        // 3) whole recurrence in ONE persistent launch
        lstm_recur<<<NCTA, 256>>>(Whh, gates, B1, B2, seq, hT, cT);
    }
}

// round 4
// speedup vs baseline: 5.0473x; 5.0473x over previous
#include <cuda_runtime.h>
#include <cuda_fp16.h>
#include <mma.h>
#include <cstdint>

using namespace nvcuda;

#define TSTEPS 512
#define BATCH  128
#define HID    1024
#define NG     4096
#define NLAYER 2
#define NCTA_R 128   // recurrence CTAs (<=148, all co-resident)
#define THR_R  128   // 4 warps

// ---------------- device scratch ----------------
__device__ float  g_gatesT[(size_t)TSTEPS * NG * BATCH];          // [t][col][b]
__device__ __align__(16) __half g_hseq16[(size_t)TSTEPS * BATCH * HID];
__device__ __align__(16) __half g_h16[2][BATCH * HID];            // ping-pong h
__device__ unsigned int g_count;

// ---------------- recurrence smem layout (bytes) ----------------
#define SM_W     0            // 1024 x 40 half   = 81920
#define SM_A     81920        // 2 x (128 x 136 half) = 69632
#define SM_G     151552       // 128 x 40 float   = 20480
#define SM_BIAS  172032       // 32 float
#define SM_TOTAL 172160

__device__ __forceinline__ uint32_t smem_u32(const void* p) {
    uint32_t a;
    asm("{ .reg .u64 t; cvta.to.shared.u64 t, %1; cvt.u32.u64 %0, t; }" : "=r"(a) : "l"(p));
    return a;
}
__device__ __forceinline__ void cp16(uint32_t dst, const void* src) {
    asm volatile("cp.async.cg.shared.global [%0], [%1], 16;" :: "r"(dst), "l"(src));
}
#define CP_COMMIT() asm volatile("cp.async.commit_group;" ::: "memory")
#define CP_WAIT1()  asm volatile("cp.async.wait_group 1;" ::: "memory")
#define CP_WAIT0()  asm volatile("cp.async.wait_group 0;" ::: "memory")

__device__ __forceinline__ float sigf(float x) { return 1.f / (1.f + __expf(-x)); }
__device__ __forceinline__ uint32_t packh2(float a, float b) {
    return (uint32_t)__half_as_ushort(__float2half_rn(a)) |
           ((uint32_t)__half_as_ushort(__float2half_rn(b)) << 16);
}

// =================================================================================
// Input GEMM (fp16 HMMA, fp32 accum): CT[t][col][b] = (A[M,1024] @ W[1024,4096])^T
// BM=128(=one timestep) BN=128 BK=32, 256 thr, 8 warps (2m x 4n), warp 64x32
// =================================================================================
template<bool AHALF>
__global__ void __launch_bounds__(256) gemm_input(const void* __restrict__ Av,
                                                  const float* __restrict__ W,
                                                  float* __restrict__ CT)
{
    __shared__ __half As[128][40];
    __shared__ __half Bs[32][136];

    const int tid  = threadIdx.x;
    const int warp = tid >> 5;
    const int wm = warp >> 2;           // 0..1
    const int wn = warp & 3;            // 0..3
    const int bm = blockIdx.y;          // timestep t
    const int bn = blockIdx.x;          // 128-col block

    const int arow = tid >> 1, acol = (tid & 1) * 16;
    const int brow = tid >> 3, bcol = (tid & 7) * 16;

    const float*  Af = (const float*) Av;
    const __half* Ah = (const __half*)Av;
    const size_t  a_off = (size_t)(bm * 128 + arow) * 1024 + acol;
    const float*  Wg = W + (size_t)brow * NG + bn * 128 + bcol;

    wmma::fragment<wmma::accumulator, 16, 16, 16, float> acc[4][2];
#pragma unroll
    for (int i = 0; i < 4; i++)
#pragma unroll
        for (int j = 0; j < 2; j++) wmma::fill_fragment(acc[i][j], 0.f);

    // prefetch k0 = 0
    float4 ra[4]; uint4 ra16[2]; float4 rb[4];
    if (AHALF) {
        ra16[0] = ((const uint4*)(Ah + a_off))[0];
        ra16[1] = ((const uint4*)(Ah + a_off))[1];
    } else {
#pragma unroll
        for (int i = 0; i < 4; i++) ra[i] = *(const float4*)(Af + a_off + i * 4);
    }
#pragma unroll
    for (int i = 0; i < 4; i++) rb[i] = *(const float4*)(Wg + i * 4);

    for (int k0 = 0; k0 < 1024; k0 += 32) {
        __syncthreads();
        if (AHALF) {
            *(uint4*)&As[arow][acol]     = ra16[0];
            *(uint4*)&As[arow][acol + 8] = ra16[1];
        } else {
            *(uint4*)&As[arow][acol] = make_uint4(
                packh2(ra[0].x, ra[0].y), packh2(ra[0].z, ra[0].w),
                packh2(ra[1].x, ra[1].y), packh2(ra[1].z, ra[1].w));
            *(uint4*)&As[arow][acol + 8] = make_uint4(
                packh2(ra[2].x, ra[2].y), packh2(ra[2].z, ra[2].w),
                packh2(ra[3].x, ra[3].y), packh2(ra[3].z, ra[3].w));
        }
        *(uint4*)&Bs[brow][bcol] = make_uint4(
            packh2(rb[0].x, rb[0].y), packh2(rb[0].z, rb[0].w),
            packh2(rb[1].x, rb[1].y), packh2(rb[1].z, rb[1].w));
        *(uint4*)&Bs[brow][bcol + 8] = make_uint4(
            packh2(rb[2].x, rb[2].y), packh2(rb[2].z, rb[2].w),
            packh2(rb[3].x, rb[3].y), packh2(rb[3].z, rb[3].w));
        __syncthreads();

        const int kn = k0 + 32;
        if (kn < 1024) {
            if (AHALF) {
                ra16[0] = ((const uint4*)(Ah + a_off + kn))[0];
                ra16[1] = ((const uint4*)(Ah + a_off + kn))[1];
            } else {
#pragma unroll
                for (int i = 0; i < 4; i++) ra[i] = *(const float4*)(Af + a_off + kn + i * 4);
            }
#pragma unroll
            for (int i = 0; i < 4; i++) rb[i] = *(const float4*)(Wg + (size_t)kn * NG + i * 4);
        }

#pragma unroll
        for (int kk = 0; kk < 32; kk += 16) {
            wmma::fragment<wmma::matrix_a, 16, 16, 16, half, wmma::row_major> fa[4];
            wmma::fragment<wmma::matrix_b, 16, 16, 16, half, wmma::row_major> fb[2];
#pragma unroll
            for (int i = 0; i < 4; i++)
                wmma::load_matrix_sync(fa[i], &As[wm * 64 + i * 16][kk], 40);
#pragma unroll
            for (int j = 0; j < 2; j++)
                wmma::load_matrix_sync(fb[j], &Bs[kk][wn * 32 + j * 16], 136);
#pragma unroll
            for (int i = 0; i < 4; i++)
#pragma unroll
                for (int j = 0; j < 2; j++)
                    wmma::mma_sync(acc[i][j], fa[i], fb[j], acc[i][j]);
        }
    }

    // transposed store: CT[t][col][b], col-major over (b, col)
    float* base = CT + (size_t)bm * NG * 128;
#pragma unroll
    for (int i = 0; i < 4; i++)
#pragma unroll
        for (int j = 0; j < 2; j++) {
            const int col = bn * 128 + wn * 32 + j * 16;
            const int b   = wm * 64 + i * 16;
            wmma::store_matrix_sync(base + (size_t)col * 128 + b, acc[i][j],
                                    128, wmma::mem_col_major);
        }
}

// =================================================================================
__global__ void lstm_init()
{
    const int i = blockIdx.x * blockDim.x + threadIdx.x;   // 65536
    if (i == 0) g_count = 0;
    ((uint32_t*)g_h16[0])[i] = 0u;
}

// =================================================================================
// Persistent fp16 HMMA recurrence. 128 CTAs x 128 threads (4 warps).
// CTA bx owns hidden cols j in [bx*8, bx*8+8), N=32 gate-cols (n = jl*4 + gate).
// W_hh slice resident in smem for all 512 steps. h staged per step via cp.async.cg
// (L1-bypassing => coherent across the global spin barrier).
// =================================================================================
__global__ void __launch_bounds__(THR_R, 1) lstm_recur(
    const float* __restrict__ Whh,      // [HID, NG]
    const float* __restrict__ gatesT,   // [T][col][b]
    const float* __restrict__ b1, const float* __restrict__ b2,
    __half* __restrict__ seq16,         // layer-0 output (or null)
    float*  __restrict__ seq32,         // last-layer output (or null)
    float* __restrict__ hT, float* __restrict__ cT)
{
    extern __shared__ __align__(16) char smem[];
    __half* Ws   = (__half*)(smem + SM_W);
    float*  Gs   = (float*) (smem + SM_G);
    float*  bias = (float*) (smem + SM_BIAS);
    const uint32_t sbase = smem_u32(smem);

    const int tid = threadIdx.x;
    const int wid = tid >> 5;
    const int j0  = blockIdx.x * 8;

    // ---- stage W slice (fp16) + bias, once ----
    for (int idx = tid; idx < 1024 * 32; idx += THR_R) {
        const int k = idx >> 5, n = idx & 31;
        const int gate = n & 3, jl = n >> 2;
        Ws[k * 40 + n] = __float2half_rn(Whh[(size_t)k * NG + gate * HID + j0 + jl]);
    }
    if (tid < 32) {
        const int gate = tid & 3, jl = tid >> 2;
        bias[tid] = b1[gate * HID + j0 + jl] + b2[gate * HID + j0 + jl];
    }
    __syncthreads();

    float c8[8];
#pragma unroll
    for (int q = 0; q < 8; q++) c8[q] = 0.f;

    const int m = tid;  // batch row for epilogue

    for (int t = 0; t < TSTEPS; ++t) {
        const __half* hin  = g_h16[t & 1];
        __half*       hout = g_h16[(t + 1) & 1];

        wmma::fragment<wmma::accumulator, 16, 16, 16, float> acc[2][2];
#pragma unroll
        for (int i = 0; i < 2; i++)
#pragma unroll
            for (int j = 0; j < 2; j++) wmma::fill_fragment(acc[i][j], 0.f);

        // stage chunk 0
        {
            const uint32_t dbase = sbase + SM_A;
#pragma unroll
            for (int u = 0; u < 16; u++) {
                const int idx = u * THR_R + tid;
                const int row = idx >> 4, k8 = (idx & 15) * 8;
                cp16(dbase + (uint32_t)(row * 136 + k8) * 2,
                     hin + (size_t)row * HID + k8);
            }
            CP_COMMIT();
        }

#pragma unroll 1
        for (int c = 0; c < 8; ++c) {
            if (c < 7) {
                const int buf = (c + 1) & 1;
                const uint32_t dbase = sbase + SM_A + buf * 34816;
                const __half* hp = hin + (c + 1) * 128;
#pragma unroll
                for (int u = 0; u < 16; u++) {
                    const int idx = u * THR_R + tid;
                    const int row = idx >> 4, k8 = (idx & 15) * 8;
                    cp16(dbase + (uint32_t)(row * 136 + k8) * 2,
                         hp + (size_t)row * HID + k8);
                }
                CP_COMMIT();
                CP_WAIT1();
            } else {
                CP_WAIT0();
            }
            __syncthreads();

            const __half* Ap = (const __half*)(smem + SM_A + (c & 1) * 34816);
            const __half* Wp = Ws + (size_t)c * 128 * 40;
#pragma unroll
            for (int kk = 0; kk < 128; kk += 16) {
                wmma::fragment<wmma::matrix_a, 16, 16, 16, half, wmma::row_major> fa[2];
                wmma::fragment<wmma::matrix_b, 16, 16, 16, half, wmma::row_major> fb[2];
#pragma unroll
                for (int i = 0; i < 2; i++)
                    wmma::load_matrix_sync(fa[i], Ap + (size_t)(wid * 32 + i * 16) * 136 + kk, 136);
#pragma unroll
                for (int j = 0; j < 2; j++)
                    wmma::load_matrix_sync(fb[j], Wp + (size_t)kk * 40 + j * 16, 40);
#pragma unroll
                for (int i = 0; i < 2; i++)
#pragma unroll
                    for (int j = 0; j < 2; j++)
                        wmma::mma_sync(acc[i][j], fa[i], fb[j], acc[i][j]);
            }
            __syncthreads();
        }

        // input-projection slice (overlaps with drain naturally via MLP)
        float gt[32];
        {
            const float* gb = gatesT + (size_t)t * NG * BATCH + m;
#pragma unroll
            for (int n = 0; n < 32; n++) {
                const int gate = n & 3, jl = n >> 2;
                gt[n] = gb[(size_t)(gate * HID + j0 + jl) * BATCH];
            }
        }

        // write gate tile to smem for remap
#pragma unroll
        for (int i = 0; i < 2; i++)
#pragma unroll
            for (int j = 0; j < 2; j++)
                wmma::store_matrix_sync(Gs + (size_t)(wid * 32 + i * 16) * 40 + j * 16,
                                        acc[i][j], 40, wmma::mem_row_major);
        __syncthreads();

        // ---- LSTM cell: thread m handles 8 hidden cols ----
        float hn[8];
#pragma unroll
        for (int q = 0; q < 8; q++) {
            const float4 v = *(const float4*)(Gs + (size_t)m * 40 + q * 4);
            const float zi = v.x + gt[q * 4 + 0] + bias[q * 4 + 0];
            const float zf = v.y + gt[q * 4 + 1] + bias[q * 4 + 1];
            const float zg = v.z + gt[q * 4 + 2] + bias[q * 4 + 2];
            const float zo = v.w + gt[q * 4 + 3] + bias[q * 4 + 3];
            const float cn = sigf(zf) * c8[q] + sigf(zi) * tanhf(zg);
            hn[q] = sigf(zo) * tanhf(cn);
            c8[q] = cn;
        }

        const size_t ob = (size_t)m * HID + j0;
        {
            uint4 u = make_uint4(packh2(hn[0], hn[1]), packh2(hn[2], hn[3]),
                                 packh2(hn[4], hn[5]), packh2(hn[6], hn[7]));
            *(uint4*)(hout + ob) = u;
            if (seq16) *(uint4*)(seq16 + (size_t)t * BATCH * HID + ob) = u;
        }
        if (seq32) {
            float4* sp = (float4*)(seq32 + (size_t)t * BATCH * HID + ob);
            sp[0] = make_float4(hn[0], hn[1], hn[2], hn[3]);
            sp[1] = make_float4(hn[4], hn[5], hn[6], hn[7]);
        }
        if (t == TSTEPS - 1) {
            float4* hp = (float4*)(hT + ob);
            hp[0] = make_float4(hn[0], hn[1], hn[2], hn[3]);
            hp[1] = make_float4(hn[4], hn[5], hn[6], hn[7]);
            float4* cp = (float4*)(cT + ob);
            cp[0] = make_float4(c8[0], c8[1], c8[2], c8[3]);
            cp[1] = make_float4(c8[4], c8[5], c8[6], c8[7]);
        }

        // ---- global generation barrier ----
        __threadfence();
        __syncthreads();
        if (tid == 0) {
            atomicAdd(&g_count, 1u);
            const unsigned target = (unsigned)(t + 1) * gridDim.x;
            while (atomicAdd(&g_count, 0u) < target) { }
        }
        __syncthreads();
    }
}

// =================================================================================
extern "C" void kernel_launch(void* const* d_in, const int* in_sizes, int n_in,
                              void* d_out, int out_size)
{
    const float* x   = (const float*)d_in[0];
    const float* wih = (const float*)d_in[1];
    const float* whh = (const float*)d_in[2];
    const float* bih = (const float*)d_in[3];
    const float* bhh = (const float*)d_in[4];
    float* out = (float*)d_out;

    cudaFuncSetAttribute(lstm_recur, cudaFuncAttributeMaxDynamicSharedMemorySize, SM_TOTAL);

    float  *gatesT;
    __half *hseq16;
    cudaGetSymbolAddress((void**)&gatesT, g_gatesT);
    cudaGetSymbolAddress((void**)&hseq16, g_hseq16);

    float* hT_base = out + (size_t)TSTEPS * BATCH * HID;
    float* cT_base = hT_base + (size_t)NLAYER * BATCH * HID;

    for (int l = 0; l < NLAYER; ++l) {
        const float* Wih = wih + (size_t)l * 1024 * NG;
        const float* Whh = whh + (size_t)l * HID * NG;
        const float* B1  = bih + (size_t)l * NG;
        const float* B2  = bhh + (size_t)l * NG;
        float* hT = hT_base + (size_t)l * BATCH * HID;
        float* cT = cT_base + (size_t)l * BATCH * HID;

        if (l == 0)
            gemm_input<false><<<dim3(NG / 128, TSTEPS), 256>>>(x, Wih, gatesT);
        else
            gemm_input<true ><<<dim3(NG / 128, TSTEPS), 256>>>(hseq16, Wih, gatesT);

        lstm_init<<<256, 256>>>();

        lstm_recur<<<NCTA_R, THR_R, SM_TOTAL>>>(
            Whh, gatesT, B1, B2,
            (l == 0) ? hseq16 : (__half*)nullptr,
            (l == 1) ? out    : (float*)nullptr,
            hT, cT);
    }
}

// round 5
// speedup vs baseline: 5.0857x; 1.0076x over previous
#include <cuda_runtime.h>
#include <cuda_fp16.h>
#include <mma.h>
#include <cstdint>

using namespace nvcuda;

#define TSTEPS 512
#define BATCH  128
#define HID    1024
#define NG     4096
#define NLAYER 2
#define NCTA_R 128   // recurrence CTAs (<=148, all co-resident)
#define THR_R  128   // 4 warps

// ---------------- device scratch ----------------
__device__ float  g_gatesT[(size_t)TSTEPS * NG * BATCH];          // [t][col][b]
__device__ __align__(16) __half g_hseq16[(size_t)TSTEPS * BATCH * HID];
__device__ __align__(16) __half g_h16[2][BATCH * HID];            // ping-pong h
__device__ unsigned int g_count;

// ---------------- recurrence smem layout (bytes) ----------------
#define SM_W     0            // 1024 x 40 half   = 81920
#define SM_A     81920        // 2 x (128 x 136 half) = 69632
#define SM_G     151552       // 128 x 40 float   = 20480
#define SM_BIAS  172032       // 32 float
#define SM_TOTAL 172160

__device__ __forceinline__ uint32_t smem_u32(const void* p) {
    uint32_t a;
    asm("{ .reg .u64 t; cvta.to.shared.u64 t, %1; cvt.u32.u64 %0, t; }" : "=r"(a) : "l"(p));
    return a;
}
__device__ __forceinline__ void cp16(uint32_t dst, const void* src) {
    asm volatile("cp.async.cg.shared.global [%0], [%1], 16;" :: "r"(dst), "l"(src));
}
#define CP_COMMIT() asm volatile("cp.async.commit_group;" ::: "memory")
#define CP_WAIT1()  asm volatile("cp.async.wait_group 1;" ::: "memory")
#define CP_WAIT0()  asm volatile("cp.async.wait_group 0;" ::: "memory")

__device__ __forceinline__ float sigf(float x) { return 1.f / (1.f + __expf(-x)); }
__device__ __forceinline__ uint32_t packh2(float a, float b) {
    return (uint32_t)__half_as_ushort(__float2half_rn(a)) |
           ((uint32_t)__half_as_ushort(__float2half_rn(b)) << 16);
}

// =================================================================================
// Input GEMM (fp16 HMMA, fp32 accum): CT[t][col][b] = (A[M,1024] @ W[1024,4096])^T
// BM=128(=one timestep) BN=128 BK=32, 256 thr, 8 warps (2m x 4n), warp 64x32
// =================================================================================
template<bool AHALF>
__global__ void __launch_bounds__(256) gemm_input(const void* __restrict__ Av,
                                                  const float* __restrict__ W,
                                                  float* __restrict__ CT)
{
    __shared__ __half As[128][40];
    __shared__ __half Bs[32][136];

    const int tid  = threadIdx.x;
    const int warp = tid >> 5;
    const int wm = warp >> 2;           // 0..1
    const int wn = warp & 3;            // 0..3
    const int bm = blockIdx.y;          // timestep t
    const int bn = blockIdx.x;          // 128-col block

    const int arow = tid >> 1, acol = (tid & 1) * 16;
    const int brow = tid >> 3, bcol = (tid & 7) * 16;

    const float*  Af = (const float*) Av;
    const __half* Ah = (const __half*)Av;
    const size_t  a_off = (size_t)(bm * 128 + arow) * 1024 + acol;
    const float*  Wg = W + (size_t)brow * NG + bn * 128 + bcol;

    wmma::fragment<wmma::accumulator, 16, 16, 16, float> acc[4][2];
#pragma unroll
    for (int i = 0; i < 4; i++)
#pragma unroll
        for (int j = 0; j < 2; j++) wmma::fill_fragment(acc[i][j], 0.f);

    // prefetch k0 = 0
    float4 ra[4]; uint4 ra16[2]; float4 rb[4];
    if (AHALF) {
        ra16[0] = ((const uint4*)(Ah + a_off))[0];
        ra16[1] = ((const uint4*)(Ah + a_off))[1];
    } else {
#pragma unroll
        for (int i = 0; i < 4; i++) ra[i] = *(const float4*)(Af + a_off + i * 4);
    }
#pragma unroll
    for (int i = 0; i < 4; i++) rb[i] = *(const float4*)(Wg + i * 4);

    for (int k0 = 0; k0 < 1024; k0 += 32) {
        __syncthreads();
        if (AHALF) {
            *(uint4*)&As[arow][acol]     = ra16[0];
            *(uint4*)&As[arow][acol + 8] = ra16[1];
        } else {
            *(uint4*)&As[arow][acol] = make_uint4(
                packh2(ra[0].x, ra[0].y), packh2(ra[0].z, ra[0].w),
                packh2(ra[1].x, ra[1].y), packh2(ra[1].z, ra[1].w));
            *(uint4*)&As[arow][acol + 8] = make_uint4(
                packh2(ra[2].x, ra[2].y), packh2(ra[2].z, ra[2].w),
                packh2(ra[3].x, ra[3].y), packh2(ra[3].z, ra[3].w));
        }
        *(uint4*)&Bs[brow][bcol] = make_uint4(
            packh2(rb[0].x, rb[0].y), packh2(rb[0].z, rb[0].w),
            packh2(rb[1].x, rb[1].y), packh2(rb[1].z, rb[1].w));
        *(uint4*)&Bs[brow][bcol + 8] = make_uint4(
            packh2(rb[2].x, rb[2].y), packh2(rb[2].z, rb[2].w),
            packh2(rb[3].x, rb[3].y), packh2(rb[3].z, rb[3].w));
        __syncthreads();

        const int kn = k0 + 32;
        if (kn < 1024) {
            if (AHALF) {
                ra16[0] = ((const uint4*)(Ah + a_off + kn))[0];
                ra16[1] = ((const uint4*)(Ah + a_off + kn))[1];
            } else {
#pragma unroll
                for (int i = 0; i < 4; i++) ra[i] = *(const float4*)(Af + a_off + kn + i * 4);
            }
#pragma unroll
            for (int i = 0; i < 4; i++) rb[i] = *(const float4*)(Wg + (size_t)kn * NG + i * 4);
        }

#pragma unroll
        for (int kk = 0; kk < 32; kk += 16) {
            wmma::fragment<wmma::matrix_a, 16, 16, 16, half, wmma::row_major> fa[4];
            wmma::fragment<wmma::matrix_b, 16, 16, 16, half, wmma::row_major> fb[2];
#pragma unroll
            for (int i = 0; i < 4; i++)
                wmma::load_matrix_sync(fa[i], &As[wm * 64 + i * 16][kk], 40);
#pragma unroll
            for (int j = 0; j < 2; j++)
                wmma::load_matrix_sync(fb[j], &Bs[kk][wn * 32 + j * 16], 136);
#pragma unroll
            for (int i = 0; i < 4; i++)
#pragma unroll
                for (int j = 0; j < 2; j++)
                    wmma::mma_sync(acc[i][j], fa[i], fb[j], acc[i][j]);
        }
    }

    // transposed store: CT[t][col][b], col-major over (b, col)
    float* base = CT + (size_t)bm * NG * 128;
#pragma unroll
    for (int i = 0; i < 4; i++)
#pragma unroll
        for (int j = 0; j < 2; j++) {
            const int col = bn * 128 + wn * 32 + j * 16;
            const int b   = wm * 64 + i * 16;
            wmma::store_matrix_sync(base + (size_t)col * 128 + b, acc[i][j],
                                    128, wmma::mem_col_major);
        }
}

// =================================================================================
__global__ void lstm_init()
{
    const int i = blockIdx.x * blockDim.x + threadIdx.x;   // 65536
    if (i == 0) g_count = 0;
    ((uint32_t*)g_h16[0])[i] = 0u;
}

// =================================================================================
// Persistent fp16 HMMA recurrence. 128 CTAs x 128 threads (4 warps).
// CTA bx owns hidden cols j in [bx*8, bx*8+8), N=32 gate-cols (n = jl*4 + gate).
// W_hh slice resident in smem for all 512 steps.
// K-chunk order STAGGERED by CTA id to avoid L2-slice hotspotting (all CTAs
// read the same 256 KB h buffer every step; lockstep linear sweeps concentrate
// on few LTS slices).
// =================================================================================
__global__ void __launch_bounds__(THR_R, 1) lstm_recur(
    const float* __restrict__ Whh,      // [HID, NG]
    const float* __restrict__ gatesT,   // [T][col][b]
    const float* __restrict__ b1, const float* __restrict__ b2,
    __half* __restrict__ seq16,         // layer-0 output (or null)
    float*  __restrict__ seq32,         // last-layer output (or null)
    float* __restrict__ hT, float* __restrict__ cT)
{
    extern __shared__ __align__(16) char smem[];
    __half* Ws   = (__half*)(smem + SM_W);
    float*  Gs   = (float*) (smem + SM_G);
    float*  bias = (float*) (smem + SM_BIAS);
    const uint32_t sbase = smem_u32(smem);

    const int tid = threadIdx.x;
    const int wid = tid >> 5;
    const int bx  = blockIdx.x;
    const int j0  = bx * 8;
    const int cfirst = bx & 7;          // staggered chunk start

    // ---- stage W slice (fp16) + bias, once ----
    for (int idx = tid; idx < 1024 * 32; idx += THR_R) {
        const int k = idx >> 5, n = idx & 31;
        const int gate = n & 3, jl = n >> 2;
        Ws[k * 40 + n] = __float2half_rn(Whh[(size_t)k * NG + gate * HID + j0 + jl]);
    }
    if (tid < 32) {
        const int gate = tid & 3, jl = tid >> 2;
        bias[tid] = b1[gate * HID + j0 + jl] + b2[gate * HID + j0 + jl];
    }
    __syncthreads();

    float c8[8];
#pragma unroll
    for (int q = 0; q < 8; q++) c8[q] = 0.f;

    const int m = tid;  // batch row for epilogue

    // A staging mapping: idx -> row, k8
    const int srow = tid >> 1;               // used via idx arithmetic below

    for (int t = 0; t < TSTEPS; ++t) {
        const __half* hin  = g_h16[t & 1];
        __half*       hout = g_h16[(t + 1) & 1];

        // ---- prefetch input-projection slice early (DRAM latency hidden under chunks) ----
        float gt[32];
        {
            const float* gb = gatesT + (size_t)t * NG * BATCH + m;
#pragma unroll
            for (int n = 0; n < 32; n++) {
                const int gate = n & 3, jl = n >> 2;
                gt[n] = gb[(size_t)(gate * HID + j0 + jl) * BATCH];
            }
        }

        wmma::fragment<wmma::accumulator, 16, 16, 16, float> acc[2][2];
#pragma unroll
        for (int i = 0; i < 2; i++)
#pragma unroll
            for (int j = 0; j < 2; j++) wmma::fill_fragment(acc[i][j], 0.f);

        // stage first chunk (cfirst) -> buf 0
        {
            const uint32_t dbase = sbase + SM_A;
            const __half* hp = hin + cfirst * 128;
#pragma unroll
            for (int u = 0; u < 16; u++) {
                const int idx = u * THR_R + tid;
                const int row = idx >> 4, k8 = (idx & 15) * 8;
                cp16(dbase + (uint32_t)(row * 136 + k8) * 2,
                     hp + (size_t)row * HID + k8);
            }
            CP_COMMIT();
        }

#pragma unroll 1
        for (int cc = 0; cc < 8; ++cc) {
            const int c = (cc + cfirst) & 7;      // actual K-chunk this iteration
            if (cc < 7) {
                const int cn = (cc + 1 + cfirst) & 7;
                const uint32_t dbase = sbase + SM_A + ((cc + 1) & 1) * 34816;
                const __half* hp = hin + cn * 128;
#pragma unroll
                for (int u = 0; u < 16; u++) {
                    const int idx = u * THR_R + tid;
                    const int row = idx >> 4, k8 = (idx & 15) * 8;
                    cp16(dbase + (uint32_t)(row * 136 + k8) * 2,
                         hp + (size_t)row * HID + k8);
                }
                CP_COMMIT();
                CP_WAIT1();
            } else {
                CP_WAIT0();
            }
            __syncthreads();

            const __half* Ap = (const __half*)(smem + SM_A + (cc & 1) * 34816);
            const __half* Wp = Ws + (size_t)c * 128 * 40;
#pragma unroll
            for (int kk = 0; kk < 128; kk += 16) {
                wmma::fragment<wmma::matrix_a, 16, 16, 16, half, wmma::row_major> fa[2];
                wmma::fragment<wmma::matrix_b, 16, 16, 16, half, wmma::row_major> fb[2];
#pragma unroll
                for (int i = 0; i < 2; i++)
                    wmma::load_matrix_sync(fa[i], Ap + (size_t)(wid * 32 + i * 16) * 136 + kk, 136);
#pragma unroll
                for (int j = 0; j < 2; j++)
                    wmma::load_matrix_sync(fb[j], Wp + (size_t)kk * 40 + j * 16, 40);
#pragma unroll
                for (int i = 0; i < 2; i++)
#pragma unroll
                    for (int j = 0; j < 2; j++)
                        wmma::mma_sync(acc[i][j], fa[i], fb[j], acc[i][j]);
            }
            __syncthreads();
        }

        // write gate tile to smem for remap
#pragma unroll
        for (int i = 0; i < 2; i++)
#pragma unroll
            for (int j = 0; j < 2; j++)
                wmma::store_matrix_sync(Gs + (size_t)(wid * 32 + i * 16) * 40 + j * 16,
                                        acc[i][j], 40, wmma::mem_row_major);
        __syncthreads();

        // ---- LSTM cell: thread m handles 8 hidden cols ----
        float hn[8];
#pragma unroll
        for (int q = 0; q < 8; q++) {
            const float4 v = *(const float4*)(Gs + (size_t)m * 40 + q * 4);
            const float zi = v.x + gt[q * 4 + 0] + bias[q * 4 + 0];
            const float zf = v.y + gt[q * 4 + 1] + bias[q * 4 + 1];
            const float zg = v.z + gt[q * 4 + 2] + bias[q * 4 + 2];
            const float zo = v.w + gt[q * 4 + 3] + bias[q * 4 + 3];
            const float cn = sigf(zf) * c8[q] + sigf(zi) * tanhf(zg);
            hn[q] = sigf(zo) * tanhf(cn);
            c8[q] = cn;
        }

        const size_t ob = (size_t)m * HID + j0;
        {
            uint4 u = make_uint4(packh2(hn[0], hn[1]), packh2(hn[2], hn[3]),
                                 packh2(hn[4], hn[5]), packh2(hn[6], hn[7]));
            *(uint4*)(hout + ob) = u;
            if (seq16) *(uint4*)(seq16 + (size_t)t * BATCH * HID + ob) = u;
        }
        if (seq32) {
            float4* sp = (float4*)(seq32 + (size_t)t * BATCH * HID + ob);
            sp[0] = make_float4(hn[0], hn[1], hn[2], hn[3]);
            sp[1] = make_float4(hn[4], hn[5], hn[6], hn[7]);
        }
        if (t == TSTEPS - 1) {
            float4* hp = (float4*)(hT + ob);
            hp[0] = make_float4(hn[0], hn[1], hn[2], hn[3]);
            hp[1] = make_float4(hn[4], hn[5], hn[6], hn[7]);
            float4* cp = (float4*)(cT + ob);
            cp[0] = make_float4(c8[0], c8[1], c8[2], c8[3]);
            cp[1] = make_float4(c8[4], c8[5], c8[6], c8[7]);
        }

        // ---- global generation barrier (arrive: one RMW; poll: plain volatile load) ----
        __threadfence();
        __syncthreads();
        if (tid == 0) {
            atomicAdd(&g_count, 1u);
            const unsigned target = (unsigned)(t + 1) * gridDim.x;
            while (*(volatile unsigned*)&g_count < target) { }
        }
        __syncthreads();
    }
}

// =================================================================================
extern "C" void kernel_launch(void* const* d_in, const int* in_sizes, int n_in,
                              void* d_out, int out_size)
{
    const float* x   = (const float*)d_in[0];
    const float* wih = (const float*)d_in[1];
    const float* whh = (const float*)d_in[2];
    const float* bih = (const float*)d_in[3];
    const float* bhh = (const float*)d_in[4];
    float* out = (float*)d_out;

    cudaFuncSetAttribute(lstm_recur, cudaFuncAttributeMaxDynamicSharedMemorySize, SM_TOTAL);

    float  *gatesT;
    __half *hseq16;
    cudaGetSymbolAddress((void**)&gatesT, g_gatesT);
    cudaGetSymbolAddress((void**)&hseq16, g_hseq16);

    float* hT_base = out + (size_t)TSTEPS * BATCH * HID;
    float* cT_base = hT_base + (size_t)NLAYER * BATCH * HID;

    for (int l = 0; l < NLAYER; ++l) {
        const float* Wih = wih + (size_t)l * 1024 * NG;
        const float* Whh = whh + (size_t)l * HID * NG;
        const float* B1  = bih + (size_t)l * NG;
        const float* B2  = bhh + (size_t)l * NG;
        float* hT = hT_base + (size_t)l * BATCH * HID;
        float* cT = cT_base + (size_t)l * BATCH * HID;

        if (l == 0)
            gemm_input<false><<<dim3(NG / 128, TSTEPS), 256>>>(x, Wih, gatesT);
        else
            gemm_input<true ><<<dim3(NG / 128, TSTEPS), 256>>>(hseq16, Wih, gatesT);

        lstm_init<<<256, 256>>>();

        lstm_recur<<<NCTA_R, THR_R, SM_TOTAL>>>(
            Whh, gatesT, B1, B2,
            (l == 0) ? hseq16 : (__half*)nullptr,
            (l == 1) ? out    : (float*)nullptr,
            hT, cT);
    }
}

// round 7
// speedup vs baseline: 5.4443x; 1.0705x over previous
#include <cuda_runtime.h>
#include <cuda_fp16.h>
#include <mma.h>
#include <cstdint>

using namespace nvcuda;

#define TSTEPS 512
#define BATCH  128
#define HID    1024
#define NG     4096
#define NLAYER 2
#define NCTA_R 128   // recurrence CTAs
#define THR_R  256   // 8 warps: 2 per SMSP for latency hiding

// ---------------- device scratch ----------------
__device__ float  g_gatesT[(size_t)TSTEPS * NG * BATCH];          // [t][col][b]
__device__ __align__(16) __half g_hseq16[(size_t)TSTEPS * BATCH * HID];
__device__ __align__(16) __half g_h16[2][BATCH * HID];            // ping-pong h
__device__ unsigned int g_count;

// ---------------- recurrence smem layout (bytes) ----------------
#define SM_W     0                    // 1024 x 40 half        = 81920
#define SM_A     81920                // 2 x (128 x 136 half)  = 69632
#define SM_G     151552               // 2 x (128 x 40 float)  = 40960
#define SM_BIAS  192512               // 32 float
#define SM_TOTAL 192640

__device__ __forceinline__ uint32_t smem_u32(const void* p) {
    uint32_t a;
    asm("{ .reg .u64 t; cvta.to.shared.u64 t, %1; cvt.u32.u64 %0, t; }" : "=r"(a) : "l"(p));
    return a;
}
__device__ __forceinline__ void cp16(uint32_t dst, const void* src) {
    asm volatile("cp.async.cg.shared.global [%0], [%1], 16;" :: "r"(dst), "l"(src));
}
#define CP_COMMIT() asm volatile("cp.async.commit_group;" ::: "memory")
#define CP_WAIT1()  asm volatile("cp.async.wait_group 1;" ::: "memory")
#define CP_WAIT0()  asm volatile("cp.async.wait_group 0;" ::: "memory")

__device__ __forceinline__ float sigf(float x) { return 1.f / (1.f + __expf(-x)); }
__device__ __forceinline__ uint32_t packh2(float a, float b) {
    return (uint32_t)__half_as_ushort(__float2half_rn(a)) |
           ((uint32_t)__half_as_ushort(__float2half_rn(b)) << 16);
}

// =================================================================================
// Input GEMM (fp16 HMMA, fp32 accum): CT[t][col][b] = (A[M,1024] @ W[1024,4096])^T
// (unchanged — controlled experiment on the recurrence)
// =================================================================================
template<bool AHALF>
__global__ void __launch_bounds__(256) gemm_input(const void* __restrict__ Av,
                                                  const float* __restrict__ W,
                                                  float* __restrict__ CT)
{
    __shared__ __half As[128][40];
    __shared__ __half Bs[32][136];

    const int tid  = threadIdx.x;
    const int warp = tid >> 5;
    const int wm = warp >> 2;
    const int wn = warp & 3;
    const int bm = blockIdx.y;
    const int bn = blockIdx.x;

    const int arow = tid >> 1, acol = (tid & 1) * 16;
    const int brow = tid >> 3, bcol = (tid & 7) * 16;

    const float*  Af = (const float*) Av;
    const __half* Ah = (const __half*)Av;
    const size_t  a_off = (size_t)(bm * 128 + arow) * 1024 + acol;
    const float*  Wg = W + (size_t)brow * NG + bn * 128 + bcol;

    wmma::fragment<wmma::accumulator, 16, 16, 16, float> acc[4][2];
#pragma unroll
    for (int i = 0; i < 4; i++)
#pragma unroll
        for (int j = 0; j < 2; j++) wmma::fill_fragment(acc[i][j], 0.f);

    float4 ra[4]; uint4 ra16[2]; float4 rb[4];
    if (AHALF) {
        ra16[0] = ((const uint4*)(Ah + a_off))[0];
        ra16[1] = ((const uint4*)(Ah + a_off))[1];
    } else {
#pragma unroll
        for (int i = 0; i < 4; i++) ra[i] = *(const float4*)(Af + a_off + i * 4);
    }
#pragma unroll
    for (int i = 0; i < 4; i++) rb[i] = *(const float4*)(Wg + i * 4);

    for (int k0 = 0; k0 < 1024; k0 += 32) {
        __syncthreads();
        if (AHALF) {
            *(uint4*)&As[arow][acol]     = ra16[0];
            *(uint4*)&As[arow][acol + 8] = ra16[1];
        } else {
            *(uint4*)&As[arow][acol] = make_uint4(
                packh2(ra[0].x, ra[0].y), packh2(ra[0].z, ra[0].w),
                packh2(ra[1].x, ra[1].y), packh2(ra[1].z, ra[1].w));
            *(uint4*)&As[arow][acol + 8] = make_uint4(
                packh2(ra[2].x, ra[2].y), packh2(ra[2].z, ra[2].w),
                packh2(ra[3].x, ra[3].y), packh2(ra[3].z, ra[3].w));
        }
        *(uint4*)&Bs[brow][bcol] = make_uint4(
            packh2(rb[0].x, rb[0].y), packh2(rb[0].z, rb[0].w),
            packh2(rb[1].x, rb[1].y), packh2(rb[1].z, rb[1].w));
        *(uint4*)&Bs[brow][bcol + 8] = make_uint4(
            packh2(rb[2].x, rb[2].y), packh2(rb[2].z, rb[2].w),
            packh2(rb[3].x, rb[3].y), packh2(rb[3].z, rb[3].w));
        __syncthreads();

        const int kn = k0 + 32;
        if (kn < 1024) {
            if (AHALF) {
                ra16[0] = ((const uint4*)(Ah + a_off + kn))[0];
                ra16[1] = ((const uint4*)(Ah + a_off + kn))[1];
            } else {
#pragma unroll
                for (int i = 0; i < 4; i++) ra[i] = *(const float4*)(Af + a_off + kn + i * 4);
            }
#pragma unroll
            for (int i = 0; i < 4; i++) rb[i] = *(const float4*)(Wg + (size_t)kn * NG + i * 4);
        }

#pragma unroll
        for (int kk = 0; kk < 32; kk += 16) {
            wmma::fragment<wmma::matrix_a, 16, 16, 16, __half, wmma::row_major> fa[4];
            wmma::fragment<wmma::matrix_b, 16, 16, 16, __half, wmma::row_major> fb[2];
#pragma unroll
            for (int i = 0; i < 4; i++)
                wmma::load_matrix_sync(fa[i], &As[wm * 64 + i * 16][kk], 40);
#pragma unroll
            for (int j = 0; j < 2; j++)
                wmma::load_matrix_sync(fb[j], &Bs[kk][wn * 32 + j * 16], 136);
#pragma unroll
            for (int i = 0; i < 4; i++)
#pragma unroll
                for (int j = 0; j < 2; j++)
                    wmma::mma_sync(acc[i][j], fa[i], fb[j], acc[i][j]);
        }
    }

    float* base = CT + (size_t)bm * NG * 128;
#pragma unroll
    for (int i = 0; i < 4; i++)
#pragma unroll
        for (int j = 0; j < 2; j++) {
            const int col = bn * 128 + wn * 32 + j * 16;
            const int b   = wm * 64 + i * 16;
            wmma::store_matrix_sync(base + (size_t)col * 128 + b, acc[i][j],
                                    128, wmma::mem_col_major);
        }
}

// =================================================================================
__global__ void lstm_init()
{
    const int i = blockIdx.x * blockDim.x + threadIdx.x;   // 65536
    if (i == 0) g_count = 0;
    ((uint32_t*)g_h16[0])[i] = 0u;
}

// =================================================================================
// Persistent fp16 HMMA recurrence. 128 CTAs x 256 threads (8 warps, 2/SMSP).
// CTA bx owns hidden cols j in [bx*8, bx*8+8), N=32 gate-cols (n = jl*4 + gate).
// K-SPLIT ACROSS WARP HALVES: warps 0-3 accumulate kk<64 of each chunk into Gs0,
// warps 4-7 accumulate kk>=64 into Gs1; cell adds the partials. 2 warps/SMSP
// hide LDSM->HMMA and sync latencies that bound the 4-warp version.
// =================================================================================
__global__ void __launch_bounds__(THR_R, 1) lstm_recur(
    const float* __restrict__ Whh,      // [HID, NG]
    const float* __restrict__ gatesT,   // [T][col][b]
    const float* __restrict__ b1, const float* __restrict__ b2,
    __half* __restrict__ seq16,         // layer-0 output (or null)
    float*  __restrict__ seq32,         // last-layer output (or null)
    float* __restrict__ hT, float* __restrict__ cT)
{
    extern __shared__ __align__(16) char smem[];
    __half* Ws   = (__half*)(smem + SM_W);
    float*  Gs0  = (float*) (smem + SM_G);
    float*  Gs1  = Gs0 + 128 * 40;
    float*  bias = (float*) (smem + SM_BIAS);
    const uint32_t sbase = smem_u32(smem);

    const int tid   = threadIdx.x;
    const int wid   = tid >> 5;
    const int mwarp = wid & 3;          // M strip: rows mwarp*32..+32
    const int khalf = wid >> 2;         // 0: kk<64, 1: kk>=64
    const int bx  = blockIdx.x;
    const int j0  = bx * 8;
    const int cfirst = bx & 7;          // staggered chunk start (harmless)

    // ---- stage W slice (fp16) + bias, once ----
    for (int idx = tid; idx < 1024 * 32; idx += THR_R) {
        const int k = idx >> 5, n = idx & 31;
        const int gate = n & 3, jl = n >> 2;
        Ws[k * 40 + n] = __float2half_rn(Whh[(size_t)k * NG + gate * HID + j0 + jl]);
    }
    if (tid < 32) {
        const int gate = tid & 3, jl = tid >> 2;
        bias[tid] = b1[gate * HID + j0 + jl] + b2[gate * HID + j0 + jl];
    }
    __syncthreads();

    // cell mapping: thread -> batch row m, 4 hidden cols (jl = nhalf*4 + q)
    const int m     = tid & 127;
    const int nhalf = tid >> 7;
    float c4[4];
#pragma unroll
    for (int q = 0; q < 4; q++) c4[q] = 0.f;

    for (int t = 0; t < TSTEPS; ++t) {
        const __half* hin  = g_h16[t & 1];
        __half*       hout = g_h16[(t + 1) & 1];

        // ---- prefetch input-projection slice (16 values, DRAM latency hidden) ----
        float gt[16];
        {
            const float* gb = gatesT + (size_t)t * NG * BATCH + m;
#pragma unroll
            for (int q = 0; q < 4; q++)
#pragma unroll
                for (int g = 0; g < 4; g++)
                    gt[q * 4 + g] = gb[(size_t)(g * HID + j0 + nhalf * 4 + q) * BATCH];
        }

        wmma::fragment<wmma::accumulator, 16, 16, 16, float> acc[2][2];
#pragma unroll
        for (int i = 0; i < 2; i++)
#pragma unroll
            for (int j = 0; j < 2; j++) wmma::fill_fragment(acc[i][j], 0.f);

        // stage first chunk -> buf 0 (8 cp16 per thread, 256 threads)
        {
            const uint32_t dbase = sbase + SM_A;
            const __half* hp = hin + cfirst * 128;
#pragma unroll
            for (int u = 0; u < 8; u++) {
                const int idx = u * THR_R + tid;
                const int row = idx >> 4, k8 = (idx & 15) * 8;
                cp16(dbase + (uint32_t)(row * 136 + k8) * 2,
                     hp + (size_t)row * HID + k8);
            }
            CP_COMMIT();
        }

#pragma unroll 1
        for (int cc = 0; cc < 8; ++cc) {
            const int c = (cc + cfirst) & 7;
            if (cc < 7) {
                const int cn = (cc + 1 + cfirst) & 7;
                const uint32_t dbase = sbase + SM_A + ((cc + 1) & 1) * 34816;
                const __half* hp = hin + cn * 128;
#pragma unroll
                for (int u = 0; u < 8; u++) {
                    const int idx = u * THR_R + tid;
                    const int row = idx >> 4, k8 = (idx & 15) * 8;
                    cp16(dbase + (uint32_t)(row * 136 + k8) * 2,
                         hp + (size_t)row * HID + k8);
                }
                CP_COMMIT();
                CP_WAIT1();
            } else {
                CP_WAIT0();
            }
            __syncthreads();

            const __half* Ap = (const __half*)(smem + SM_A + (cc & 1) * 34816)
                             + (size_t)mwarp * 32 * 136 + khalf * 64;
            const __half* Wp = Ws + (size_t)(c * 128 + khalf * 64) * 40;
#pragma unroll
            for (int kk = 0; kk < 64; kk += 16) {
                wmma::fragment<wmma::matrix_a, 16, 16, 16, __half, wmma::row_major> fa[2];
                wmma::fragment<wmma::matrix_b, 16, 16, 16, __half, wmma::row_major> fb[2];
#pragma unroll
                for (int i = 0; i < 2; i++)
                    wmma::load_matrix_sync(fa[i], Ap + (size_t)(i * 16) * 136 + kk, 136);
#pragma unroll
                for (int j = 0; j < 2; j++)
                    wmma::load_matrix_sync(fb[j], Wp + (size_t)kk * 40 + j * 16, 40);
#pragma unroll
                for (int i = 0; i < 2; i++)
#pragma unroll
                    for (int j = 0; j < 2; j++)
                        wmma::mma_sync(acc[i][j], fa[i], fb[j], acc[i][j]);
            }
            __syncthreads();
        }

        // ---- write partial gate tiles ----
        float* Gsw = khalf ? Gs1 : Gs0;
#pragma unroll
        for (int i = 0; i < 2; i++)
#pragma unroll
            for (int j = 0; j < 2; j++)
                wmma::store_matrix_sync(Gsw + (size_t)(mwarp * 32 + i * 16) * 40 + j * 16,
                                        acc[i][j], 40, wmma::mem_row_major);
        __syncthreads();

        // ---- LSTM cell: thread handles (m, 4 hidden cols) ----
        float hn[4];
#pragma unroll
        for (int q = 0; q < 4; q++) {
            const int n = nhalf * 16 + q * 4;
            const float4 v0 = *(const float4*)(Gs0 + (size_t)m * 40 + n);
            const float4 v1 = *(const float4*)(Gs1 + (size_t)m * 40 + n);
            const float zi = v0.x + v1.x + gt[q * 4 + 0] + bias[n + 0];
            const float zf = v0.y + v1.y + gt[q * 4 + 1] + bias[n + 1];
            const float zg = v0.z + v1.z + gt[q * 4 + 2] + bias[n + 2];
            const float zo = v0.w + v1.w + gt[q * 4 + 3] + bias[n + 3];
            const float cn = sigf(zf) * c4[q] + sigf(zi) * tanhf(zg);
            hn[q] = sigf(zo) * tanhf(cn);
            c4[q] = cn;
        }

        const size_t ob = (size_t)m * HID + j0 + nhalf * 4;
        {
            uint2 u = make_uint2(packh2(hn[0], hn[1]), packh2(hn[2], hn[3]));
            *(uint2*)(hout + ob) = u;
            if (seq16) *(uint2*)(seq16 + (size_t)t * BATCH * HID + ob) = u;
        }
        if (seq32)
            *(float4*)(seq32 + (size_t)t * BATCH * HID + ob) =
                make_float4(hn[0], hn[1], hn[2], hn[3]);
        if (t == TSTEPS - 1) {
            *(float4*)(hT + ob) = make_float4(hn[0], hn[1], hn[2], hn[3]);
            *(float4*)(cT + ob) = make_float4(c4[0], c4[1], c4[2], c4[3]);
        }

        // ---- global generation barrier ----
        __threadfence();
        __syncthreads();
        if (tid == 0) {
            atomicAdd(&g_count, 1u);
            const unsigned target = (unsigned)(t + 1) * gridDim.x;
            while (*(volatile unsigned*)&g_count < target) { }
        }
        __syncthreads();
    }
}

// =================================================================================
extern "C" void kernel_launch(void* const* d_in, const int* in_sizes, int n_in,
                              void* d_out, int out_size)
{
    const float* x   = (const float*)d_in[0];
    const float* wih = (const float*)d_in[1];
    const float* whh = (const float*)d_in[2];
    const float* bih = (const float*)d_in[3];
    const float* bhh = (const float*)d_in[4];
    float* out = (float*)d_out;

    cudaFuncSetAttribute(lstm_recur, cudaFuncAttributeMaxDynamicSharedMemorySize, SM_TOTAL);

    float  *gatesT;
    __half *hseq16;
    cudaGetSymbolAddress((void**)&gatesT, g_gatesT);
    cudaGetSymbolAddress((void**)&hseq16, g_hseq16);

    float* hT_base = out + (size_t)TSTEPS * BATCH * HID;
    float* cT_base = hT_base + (size_t)NLAYER * BATCH * HID;

    for (int l = 0; l < NLAYER; ++l) {
        const float* Wih = wih + (size_t)l * 1024 * NG;
        const float* Whh = whh + (size_t)l * HID * NG;
        const float* B1  = bih + (size_t)l * NG;
        const float* B2  = bhh + (size_t)l * NG;
        float* hT = hT_base + (size_t)l * BATCH * HID;
        float* cT = cT_base + (size_t)l * BATCH * HID;

        if (l == 0)
            gemm_input<false><<<dim3(NG / 128, TSTEPS), 256>>>(x, Wih, gatesT);
        else
            gemm_input<true ><<<dim3(NG / 128, TSTEPS), 256>>>(hseq16, Wih, gatesT);

        lstm_init<<<256, 256>>>();

        lstm_recur<<<NCTA_R, THR_R, SM_TOTAL>>>(
            Whh, gatesT, B1, B2,
            (l == 0) ? hseq16 : (__half*)nullptr,
            (l == 1) ? out    : (float*)nullptr,
            hT, cT);
    }
}